// round 13
// baseline (speedup 1.0000x reference)
#include <cuda_runtime.h>
#include <cuda_fp16.h>
#include <cstdint>

// Problem dims (fixed by reference)
#define B_   2
#define S_   2048
#define D_   1024
#define E_   1024
#define H_   16
#define HD_  64
#define MTOT (B_*S_)        // 4096
#define NQKV (3*E_)         // 3072
#define BHN  (B_*H_)        // 32

// log2(e)/64 folded into q so exp(s/64) == exp2(q'.k)
#define QSC 0.0225421246528f

// ---- static device scratch (no allocations allowed) ----
__device__ __align__(256) __half g_q[(size_t)BHN * S_ * HD_];     // [bh][s][d], pre-scaled by QSC
__device__ __align__(256) __half g_k[(size_t)BHN * S_ * HD_];     // [bh][s][d]
__device__ __align__(256) __half g_vt[(size_t)BHN * HD_ * S_];    // [bh][d][s]  (transposed)
__device__ __align__(256) __half g_vals[(size_t)MTOT * E_];       // O, fp16
__device__ __align__(256) __half g_x_h[(size_t)MTOT * D_];
__device__ __align__(256) __half g_wqkv_h[(size_t)NQKV * D_];
__device__ __align__(256) __half g_wout_h[(size_t)D_ * E_];
__device__ __align__(256) float  g_out_scratch[(size_t)MTOT * D_];
__device__ __align__(256) float  g_attn_scratch[(size_t)BHN * S_ * S_];

__device__ __forceinline__ uint32_t h2u(__half2 h) { return *reinterpret_cast<uint32_t*>(&h); }

__device__ __forceinline__ float ex2f(float x) {
    float y;
    asm("ex2.approx.f32 %0, %1;" : "=f"(y) : "f"(x));
    return y;
}

__device__ __forceinline__ void mma_f16(float c[4], const uint32_t a[4], const uint32_t b[2]) {
    asm volatile(
        "mma.sync.aligned.m16n8k16.row.col.f32.f16.f16.f32 "
        "{%0,%1,%2,%3}, {%4,%5,%6,%7}, {%8,%9}, {%0,%1,%2,%3};\n"
        : "+f"(c[0]), "+f"(c[1]), "+f"(c[2]), "+f"(c[3])
        : "r"(a[0]), "r"(a[1]), "r"(a[2]), "r"(a[3]), "r"(b[0]), "r"(b[1]));
}

__device__ __forceinline__ void cpa16(void* s, const void* g) {
    uint32_t sa = (uint32_t)__cvta_generic_to_shared(s);
    asm volatile("cp.async.cg.shared.global [%0], [%1], 16;" :: "r"(sa), "l"(g));
}
__device__ __forceinline__ void cpa4(void* s, const void* g) {
    uint32_t sa = (uint32_t)__cvta_generic_to_shared(s);
    asm volatile("cp.async.ca.shared.global [%0], [%1], 4;" :: "r"(sa), "l"(g));
}
#define CP_COMMIT asm volatile("cp.async.commit_group;")
#define CP_WAIT0  asm volatile("cp.async.wait_group 0;")
#define CP_WAIT2  asm volatile("cp.async.wait_group 2;")

__device__ __forceinline__ void stg_cs_v4(float* p, float a, float b, float c, float d) {
    asm volatile("st.global.cs.v4.f32 [%0], {%1,%2,%3,%4};"
                 :: "l"(p), "f"(a), "f"(b), "f"(c), "f"(d));
}

// ============================================================================
// fp32 -> fp16 conversion for x, w_qkv, w_out in ONE launch (8 elems/thread)
// ============================================================================
__global__ void cvt_all(const float* __restrict__ x, const float* __restrict__ wq,
                        const float* __restrict__ wo) {
    const long long N1 = (long long)MTOT * D_;
    const long long N2 = N1 + (long long)NQKV * D_;
    const long long N3 = N2 + (long long)D_ * E_;
    long long i = ((long long)blockIdx.x * blockDim.x + threadIdx.x) * 8;
    if (i >= N3) return;
    const float* in;
    __half* out;
    long long off;
    if (i < N1)      { in = x;  out = g_x_h;    off = i; }
    else if (i < N2) { in = wq; out = g_wqkv_h; off = i - N1; }
    else             { in = wo; out = g_wout_h; off = i - N2; }
    float4 a = *reinterpret_cast<const float4*>(in + off);
    float4 b = *reinterpret_cast<const float4*>(in + off + 4);
    uint4 u;
    u.x = h2u(__floats2half2_rn(a.x, a.y));
    u.y = h2u(__floats2half2_rn(a.z, a.w));
    u.z = h2u(__floats2half2_rn(b.x, b.y));
    u.w = h2u(__floats2half2_rn(b.z, b.w));
    *reinterpret_cast<uint4*>(out + off) = u;
}

// ============================================================================
// Dense GEMMs, fp16 mma m16n8k16, fp32 accum, 4-stage cp.async pipeline.
// MODE 0: qkv — +bias; q scaled by QSC; q/k row-major fp16; v transposed fp16.
// MODE 3: proj — +bias -> out (fp32)
// ============================================================================
#define GSTAGES 4
#define GSAS 20
#define GEMM_SMEM (GSTAGES * 2 * 128 * GSAS * 4)

template<int MODE>
__global__ __launch_bounds__(256)
void mma_gemm(const float* __restrict__ bias, float* __restrict__ pC) {
    constexpr int KDIM = 1024;
    constexpr int KT = KDIM / 32;

    extern __shared__ uint32_t smg[];

    const int tid = threadIdx.x;
    const int wid = tid >> 5, lane = tid & 31;
    const int g = lane >> 2, tg = lane & 3;
    const int warpM = wid / 4, warpN = wid % 4;
    const int bm = blockIdx.y * 128;
    const int bn = blockIdx.x * 128;

    const __half* gA = (MODE == 0) ? g_x_h : g_vals;
    const __half* gB = (MODE == 0) ? g_wqkv_h : g_wout_h;

    const int lrow = tid >> 2, lch = tid & 3;

    auto issue_stage = [&](int kt, int s) {
        uint32_t* As = smg + (size_t)s * 2 * 128 * GSAS;
        uint32_t* Bs = As + 128 * GSAS;
        #pragma unroll
        for (int rep = 0; rep < 2; rep++) {
            int row = rep * 64 + lrow;
            cpa16(&As[row * GSAS + lch * 4], gA + (size_t)(bm + row) * KDIM + kt * 32 + lch * 8);
            cpa16(&Bs[row * GSAS + lch * 4], gB + (size_t)(bn + row) * KDIM + kt * 32 + lch * 8);
        }
        CP_COMMIT;
    };

    #pragma unroll
    for (int s = 0; s < GSTAGES - 1; s++) issue_stage(s, s);

    float acc[4][4][4] = {};

    #pragma unroll 1
    for (int kt = 0; kt < KT; kt++) {
        if (kt < KT - 2) { CP_WAIT2; } else { CP_WAIT0; }
        __syncthreads();

        const uint32_t* As = smg + (size_t)(kt % GSTAGES) * 2 * 128 * GSAS;
        const uint32_t* Bs = As + 128 * GSAS;

        #pragma unroll
        for (int ks = 0; ks < 2; ks++) {
            const int kb = ks * 8;
            uint32_t af[4][4], bfr[4][2];
            #pragma unroll
            for (int i = 0; i < 4; i++) {
                const int rm = warpM * 64 + i * 16;
                af[i][0] = As[(rm + g) * GSAS + kb + tg];
                af[i][1] = As[(rm + g + 8) * GSAS + kb + tg];
                af[i][2] = As[(rm + g) * GSAS + kb + tg + 4];
                af[i][3] = As[(rm + g + 8) * GSAS + kb + tg + 4];
            }
            #pragma unroll
            for (int j = 0; j < 4; j++) {
                const int cn = warpN * 32 + j * 8;
                bfr[j][0] = Bs[(cn + g) * GSAS + kb + tg];
                bfr[j][1] = Bs[(cn + g) * GSAS + kb + tg + 4];
            }
            #pragma unroll
            for (int i = 0; i < 4; i++)
                #pragma unroll
                for (int j = 0; j < 4; j++)
                    mma_f16(acc[i][j], af[i], bfr[j]);
        }

        if (kt + GSTAGES - 1 < KT) issue_stage(kt + GSTAGES - 1, (kt + GSTAGES - 1) % GSTAGES);
    }

    #pragma unroll
    for (int i = 0; i < 4; i++) {
        const int rm = bm + warpM * 64 + i * 16;
        const int r0 = rm + g, r1 = rm + g + 8;
        #pragma unroll
        for (int j = 0; j < 4; j++) {
            const int n0 = bn + warpN * 32 + j * 8;
            const int nc = n0 + 2 * tg;
            float c0 = acc[i][j][0] + bias[nc], c1 = acc[i][j][1] + bias[nc + 1];
            float c2 = acc[i][j][2] + bias[nc], c3 = acc[i][j][3] + bias[nc + 1];
            if (MODE == 0) {
                const int h = n0 / (3 * HD_);
                const int which = (n0 % (3 * HD_)) / HD_;
                const int d = (n0 % HD_) + 2 * tg;
                const int bb = r0 >> 11;
                const int ss0 = r0 & (S_ - 1), ss1 = r1 & (S_ - 1);
                if (which == 0) {       // q: pre-scale so exp(s/64) = exp2(q'.k)
                    size_t base = (((size_t)bb * H_ + h) * S_) * HD_ + d;
                    *reinterpret_cast<__half2*>(g_q + base + (size_t)ss0 * HD_) =
                        __floats2half2_rn(c0 * QSC, c1 * QSC);
                    *reinterpret_cast<__half2*>(g_q + base + (size_t)ss1 * HD_) =
                        __floats2half2_rn(c2 * QSC, c3 * QSC);
                } else if (which == 1) {
                    size_t base = (((size_t)bb * H_ + h) * S_) * HD_ + d;
                    *reinterpret_cast<__half2*>(g_k + base + (size_t)ss0 * HD_) = __floats2half2_rn(c0, c1);
                    *reinterpret_cast<__half2*>(g_k + base + (size_t)ss1 * HD_) = __floats2half2_rn(c2, c3);
                } else {
                    size_t base = ((size_t)bb * H_ + h) * HD_;
                    g_vt[(base + d) * S_ + ss0]     = __float2half_rn(c0);
                    g_vt[(base + d + 1) * S_ + ss0] = __float2half_rn(c1);
                    g_vt[(base + d) * S_ + ss1]     = __float2half_rn(c2);
                    g_vt[(base + d + 1) * S_ + ss1] = __float2half_rn(c3);
                }
            } else {
                float* outp = pC ? pC : g_out_scratch;
                *reinterpret_cast<float2*>(outp + (size_t)r0 * D_ + nc) = make_float2(c0, c1);
                *reinterpret_cast<float2*>(outp + (size_t)r1 * D_ + nc) = make_float2(c2, c3);
            }
        }
    }
}

// ============================================================================
// Fused attention with PERMUTED K columns so each thread owns 32 consecutive
// attn cols -> st.cs.v4 (halves STG issue). V^T smem k-words permuted with
// the matching map so PV mma stays correct. Pass 1 is permutation-invariant.
//   K smem row R holds global K row pi(R) = 32*((R>>1)&3) + 2*(R>>3) + (R&1)
//   fragment (tile j, pair tg, b) -> attn col 32*tg + 2*j + b
//   V^T smem word W holds s-pair s0(W) = 32*(W&3) + 4*(W>>3) + 2*((W>>2)&1)
// ============================================================================
#define QSTR 36
#define KSTR 36
#define VSTR 68
#define NKT (S_ / 128)                     // 16
#define KS_OFF (128 * QSTR)
#define VS_OFF (KS_OFF + 2 * 128 * KSTR)
#define FA_SMEM ((128*QSTR + 2*128*KSTR + 2*64*VSTR) * 4)   // 90112 B

__global__ __launch_bounds__(256, 2)
void fused_attn(float* __restrict__ attn_ext) {
    extern __shared__ uint32_t sm[];
    uint32_t* Qs = sm;                     // 128 x 36
    uint32_t* Ks = sm + KS_OFF;            // 2 x 128 x 36
    uint32_t* Vs = sm + VS_OFF;            // 2 x 64 x 68

    const int tid = threadIdx.x;
    const int wid = tid >> 5, lane = tid & 31;
    const int g = lane >> 2, tg = lane & 3;
    const int wm = wid * 16;               // warp's 16 q-rows
    const int bm = blockIdx.x * 128;
    const int bh = blockIdx.y;

    const __half* gQ  = g_q  + (size_t)bh * S_ * HD_ + (size_t)bm * HD_;
    const __half* gK  = g_k  + (size_t)bh * S_ * HD_;
    const __half* gVt = g_vt + (size_t)bh * HD_ * S_;
    float* attnp = (attn_ext ? attn_ext : g_attn_scratch) + (size_t)bh * S_ * S_;

    auto load_q = [&]() {
        #pragma unroll
        for (int rep = 0; rep < 4; rep++) {
            int idx = rep * 256 + tid, row = idx >> 3, ch = idx & 7;
            cpa16(&Qs[row * QSTR + ch * 4], gQ + (size_t)row * HD_ + ch * 8);
        }
    };
    // K rows permuted: smem row R <- global row pi(R)
    auto load_k = [&](int kt, int b) {
        const __half* base = gK + (size_t)kt * 128 * HD_;
        #pragma unroll
        for (int rep = 0; rep < 4; rep++) {
            int idx = rep * 256 + tid, row = idx >> 3, ch = idx & 7;
            int prow = 32 * ((row >> 1) & 3) + 2 * (row >> 3) + (row & 1);
            cpa16(&Ks[b * 128 * KSTR + row * KSTR + ch * 4], base + (size_t)prow * HD_ + ch * 8);
        }
    };
    // V^T tile: 64 d-rows x 64 k-words; word W <- s-pair s0(W) (4B cp.async)
    auto load_v = [&](int kt, int b) {
        const __half* base = gVt + (size_t)kt * 128;
        #pragma unroll
        for (int rep = 0; rep < 16; rep++) {
            int idx = rep * 256 + tid;
            int row = idx >> 6, W = idx & 63;
            int s0 = 32 * (W & 3) + 4 * (W >> 3) + 2 * ((W >> 2) & 1);
            cpa4(&Vs[b * 64 * VSTR + row * VSTR + W], base + (size_t)row * S_ + s0);
        }
    };

    // S(16x64 half) = Q'_warp @ K^T over n8 tiles [jbase, jbase+8)
    auto compute_S_half = [&](const uint32_t* Kb, float sacc[8][4], int jbase) {
        #pragma unroll
        for (int j = 0; j < 8; j++)
            #pragma unroll
            for (int e = 0; e < 4; e++) sacc[j][e] = 0.0f;
        #pragma unroll
        for (int ks = 0; ks < 4; ks++) {
            const int kb = ks * 8;
            uint32_t af[4];
            af[0] = Qs[(wm + g) * QSTR + kb + tg];
            af[1] = Qs[(wm + g + 8) * QSTR + kb + tg];
            af[2] = Qs[(wm + g) * QSTR + kb + tg + 4];
            af[3] = Qs[(wm + g + 8) * QSTR + kb + tg + 4];
            #pragma unroll
            for (int j = 0; j < 8; j++) {
                uint32_t bf[2];
                bf[0] = Kb[(8 * (jbase + j) + g) * KSTR + kb + tg];
                bf[1] = Kb[(8 * (jbase + j) + g) * KSTR + kb + tg + 4];
                mma_f16(sacc[j], af, bf);
            }
        }
    };

    // ---- prologue ----
    load_q();
    load_k(0, 0);
    CP_COMMIT;
    CP_WAIT0;
    __syncthreads();

    // ================= pass 1: row sums of exp2 (registers only) ============
    float lp0 = 0.0f, lp1 = 0.0f;
    int b = 0;
    #pragma unroll 1
    for (int kt = 0; kt < NKT; kt++) {
        if (kt < NKT - 1) { load_k(kt + 1, b ^ 1); CP_COMMIT; }
        #pragma unroll
        for (int half = 0; half < 2; half++) {
            float sacc[8][4];
            compute_S_half(Ks + b * 128 * KSTR, sacc, half * 8);
            #pragma unroll
            for (int j = 0; j < 8; j++) {
                lp0 += ex2f(sacc[j][0]) + ex2f(sacc[j][1]);
                lp1 += ex2f(sacc[j][2]) + ex2f(sacc[j][3]);
            }
        }
        if (kt < NKT - 1) { CP_WAIT0; __syncthreads(); b ^= 1; }
    }
    lp0 += __shfl_xor_sync(0xffffffff, lp0, 1);
    lp0 += __shfl_xor_sync(0xffffffff, lp0, 2);
    lp1 += __shfl_xor_sync(0xffffffff, lp1, 1);
    lp1 += __shfl_xor_sync(0xffffffff, lp1, 2);
    const float li0 = 1.0f / lp0;          // row wm+g
    const float li1 = 1.0f / lp1;          // row wm+g+8

    // ================= pass 2: attn write (v4) + O accumulation =============
    load_k(0, 0); load_v(0, 0);
    CP_COMMIT;
    CP_WAIT0;
    __syncthreads();

    float oacc[8][4] = {};
    b = 0;
    #pragma unroll 1
    for (int kt = 0; kt < NKT; kt++) {
        if (kt < NKT - 1) { load_k(kt + 1, b ^ 1); load_v(kt + 1, b ^ 1); CP_COMMIT; }
        const uint32_t* Kb = Ks + b * 128 * KSTR;
        const uint32_t* Vb = Vs + b * 64 * VSTR;
        float* arow0 = attnp + (size_t)(bm + wm + g) * S_ + kt * 128 + 32 * tg;
        float* arow1 = attnp + (size_t)(bm + wm + g + 8) * S_ + kt * 128 + 32 * tg;

        #pragma unroll
        for (int half = 0; half < 2; half++) {
            float sacc[8][4];
            compute_S_half(Kb, sacc, half * 8);

            uint32_t paf[4][4];
            #pragma unroll
            for (int q = 0; q < 4; q++) {
                float p00 = ex2f(sacc[2*q][0]) * li0;     // row g,   col 4c+0
                float p01 = ex2f(sacc[2*q][1]) * li0;     //          col 4c+1
                float p02 = ex2f(sacc[2*q][2]) * li1;     // row g+8
                float p03 = ex2f(sacc[2*q][3]) * li1;
                float p10 = ex2f(sacc[2*q+1][0]) * li0;   // row g,   col 4c+2
                float p11 = ex2f(sacc[2*q+1][1]) * li0;   //          col 4c+3
                float p12 = ex2f(sacc[2*q+1][2]) * li1;
                float p13 = ex2f(sacc[2*q+1][3]) * li1;
                const int col = 16 * half + 4 * q;
                stg_cs_v4(arow0 + col, p00, p01, p10, p11);
                stg_cs_v4(arow1 + col, p02, p03, p12, p13);
                paf[q][0] = h2u(__floats2half2_rn(p00, p01));  // row g,   k-word tg
                paf[q][1] = h2u(__floats2half2_rn(p02, p03));  // row g+8, k-word tg
                paf[q][2] = h2u(__floats2half2_rn(p10, p11));  // row g,   k-word tg+4
                paf[q][3] = h2u(__floats2half2_rn(p12, p13));  // row g+8, k-word tg+4
            }
            // O += P_half @ V (k16 chunks c = half*4+q; V words permuted to match)
            #pragma unroll
            for (int q = 0; q < 4; q++) {
                const int kb = (half * 4 + q) * 8;
                #pragma unroll
                for (int jn = 0; jn < 8; jn++) {
                    uint32_t bf[2];
                    bf[0] = Vb[(8 * jn + g) * VSTR + kb + tg];
                    bf[1] = Vb[(8 * jn + g) * VSTR + kb + tg + 4];
                    mma_f16(oacc[jn], paf[q], bf);
                }
            }
        }
        if (kt < NKT - 1) { CP_WAIT0; __syncthreads(); b ^= 1; }
    }

    // ---- epilogue: O (16x64 per warp) -> g_vals fp16 ----
    const int bb = bh >> 4, h = bh & 15;
    __half* vbase = g_vals + (size_t)bb * S_ * E_ + (size_t)h * HD_;
    const int r0 = bm + wm + g, r1 = r0 + 8;
    #pragma unroll
    for (int jn = 0; jn < 8; jn++) {
        const int cn = 8 * jn + 2 * tg;
        *reinterpret_cast<__half2*>(vbase + (size_t)r0 * E_ + cn) =
            __floats2half2_rn(oacc[jn][0], oacc[jn][1]);
        *reinterpret_cast<__half2*>(vbase + (size_t)r1 * E_ + cn) =
            __floats2half2_rn(oacc[jn][2], oacc[jn][3]);
    }
}

// ============================================================================
// Launch. Inputs: x, w_qkv, b_qkv, w_out, b_out.
// ============================================================================
extern "C" void kernel_launch(void* const* d_in, const int* in_sizes, int n_in,
                              void* d_out, int out_size) {
    const float* x     = (const float*)d_in[0];
    const float* w_qkv = (const float*)d_in[1];
    const float* b_qkv = (const float*)d_in[2];
    const float* w_out = (const float*)d_in[3];
    const float* b_out = (const float*)d_in[4];
    float* dout = (float*)d_out;

    const long long OUTN  = (long long)MTOT * D_;
    const long long ATTNN = (long long)BHN * S_ * S_;
    float* out_ext  = nullptr;
    float* attn_ext = nullptr;
    const long long osz = (long long)out_size;
    if (osz >= OUTN + ATTNN) { out_ext = dout; attn_ext = dout + OUTN; }
    else if (osz == ATTNN)   { attn_ext = dout; }
    else                     { out_ext = dout; }

    cudaFuncSetAttribute(fused_attn, cudaFuncAttributeMaxDynamicSharedMemorySize, FA_SMEM);
    cudaFuncSetAttribute(mma_gemm<0>, cudaFuncAttributeMaxDynamicSharedMemorySize, GEMM_SMEM);
    cudaFuncSetAttribute(mma_gemm<3>, cudaFuncAttributeMaxDynamicSharedMemorySize, GEMM_SMEM);

    const long long CVT_N = (long long)MTOT * D_ + (long long)NQKV * D_ + (long long)D_ * E_;
    dim3 t(256);
    cvt_all<<<(unsigned)((CVT_N / 8 + 255) / 256), t>>>(x, w_qkv, w_out);

    mma_gemm<0><<<dim3(NQKV / 128, MTOT / 128), t, GEMM_SMEM>>>(b_qkv, nullptr);
    fused_attn<<<dim3(S_ / 128, BHN), t, FA_SMEM>>>(attn_ext);
    mma_gemm<3><<<dim3(D_ / 128, MTOT / 128), t, GEMM_SMEM>>>(b_out, out_ext);
}

// round 15
// speedup vs baseline: 1.2187x; 1.2187x over previous
#include <cuda_runtime.h>
#include <cuda_fp16.h>
#include <cstdint>

// Problem dims (fixed by reference)
#define B_   2
#define S_   2048
#define D_   1024
#define E_   1024
#define H_   16
#define HD_  64
#define MTOT (B_*S_)        // 4096
#define NQKV (3*E_)         // 3072
#define BHN  (B_*H_)        // 32

// log2(e)/64 folded into q so exp(s/64) == exp2(q'.k)
#define QSC 0.0225421246528f

// ---- static device scratch (no allocations allowed) ----
__device__ __align__(256) __half g_q[(size_t)BHN * S_ * HD_];     // [bh][s][d], pre-scaled by QSC
__device__ __align__(256) __half g_k[(size_t)BHN * S_ * HD_];     // [bh][s][d]
__device__ __align__(256) __half g_vt[(size_t)BHN * HD_ * S_];    // [bh][d][s]  (transposed)
__device__ __align__(256) __half g_vals[(size_t)MTOT * E_];       // O, fp16
__device__ __align__(256) __half g_x_h[(size_t)MTOT * D_];
__device__ __align__(256) __half g_wqkv_h[(size_t)NQKV * D_];
__device__ __align__(256) __half g_wout_h[(size_t)D_ * E_];
__device__ __align__(256) float  g_out_scratch[(size_t)MTOT * D_];
__device__ __align__(256) float  g_attn_scratch[(size_t)BHN * S_ * S_];

__device__ __forceinline__ uint32_t h2u(__half2 h) { return *reinterpret_cast<uint32_t*>(&h); }

__device__ __forceinline__ float ex2f(float x) {
    float y;
    asm("ex2.approx.f32 %0, %1;" : "=f"(y) : "f"(x));
    return y;
}

__device__ __forceinline__ void mma_f16(float c[4], const uint32_t a[4], const uint32_t b[2]) {
    asm volatile(
        "mma.sync.aligned.m16n8k16.row.col.f32.f16.f16.f32 "
        "{%0,%1,%2,%3}, {%4,%5,%6,%7}, {%8,%9}, {%0,%1,%2,%3};\n"
        : "+f"(c[0]), "+f"(c[1]), "+f"(c[2]), "+f"(c[3])
        : "r"(a[0]), "r"(a[1]), "r"(a[2]), "r"(a[3]), "r"(b[0]), "r"(b[1]));
}

__device__ __forceinline__ void cpa16(void* s, const void* g) {
    uint32_t sa = (uint32_t)__cvta_generic_to_shared(s);
    asm volatile("cp.async.cg.shared.global [%0], [%1], 16;" :: "r"(sa), "l"(g));
}
#define CP_COMMIT asm volatile("cp.async.commit_group;")
#define CP_WAIT0  asm volatile("cp.async.wait_group 0;")
#define CP_WAIT2  asm volatile("cp.async.wait_group 2;")

__device__ __forceinline__ void stg_cs_v2(float* p, float a, float b) {
    asm volatile("st.global.cs.v2.f32 [%0], {%1,%2};" :: "l"(p), "f"(a), "f"(b));
}

// ============================================================================
// fp32 -> fp16 conversion for x, w_qkv, w_out in ONE launch (8 elems/thread)
// ============================================================================
__global__ void cvt_all(const float* __restrict__ x, const float* __restrict__ wq,
                        const float* __restrict__ wo) {
    const long long N1 = (long long)MTOT * D_;
    const long long N2 = N1 + (long long)NQKV * D_;
    const long long N3 = N2 + (long long)D_ * E_;
    long long i = ((long long)blockIdx.x * blockDim.x + threadIdx.x) * 8;
    if (i >= N3) return;
    const float* in;
    __half* out;
    long long off;
    if (i < N1)      { in = x;  out = g_x_h;    off = i; }
    else if (i < N2) { in = wq; out = g_wqkv_h; off = i - N1; }
    else             { in = wo; out = g_wout_h; off = i - N2; }
    float4 a = *reinterpret_cast<const float4*>(in + off);
    float4 b = *reinterpret_cast<const float4*>(in + off + 4);
    uint4 u;
    u.x = h2u(__floats2half2_rn(a.x, a.y));
    u.y = h2u(__floats2half2_rn(a.z, a.w));
    u.z = h2u(__floats2half2_rn(b.x, b.y));
    u.w = h2u(__floats2half2_rn(b.z, b.w));
    *reinterpret_cast<uint4*>(out + off) = u;
}

// ============================================================================
// Dense GEMMs, fp16 mma m16n8k16, fp32 accum, 4-stage cp.async pipeline.
// MODE 0: qkv — +bias; q scaled by QSC; q/k row-major fp16; v transposed fp16.
// MODE 3: proj — +bias -> out (fp32)
// ============================================================================
#define GSTAGES 4
#define GSAS 20
#define GEMM_SMEM (GSTAGES * 2 * 128 * GSAS * 4)

template<int MODE>
__global__ __launch_bounds__(256)
void mma_gemm(const float* __restrict__ bias, float* __restrict__ pC) {
    constexpr int KDIM = 1024;
    constexpr int KT = KDIM / 32;

    extern __shared__ uint32_t smg[];

    const int tid = threadIdx.x;
    const int wid = tid >> 5, lane = tid & 31;
    const int g = lane >> 2, tg = lane & 3;
    const int warpM = wid / 4, warpN = wid % 4;
    const int bm = blockIdx.y * 128;
    const int bn = blockIdx.x * 128;

    const __half* gA = (MODE == 0) ? g_x_h : g_vals;
    const __half* gB = (MODE == 0) ? g_wqkv_h : g_wout_h;

    const int lrow = tid >> 2, lch = tid & 3;

    auto issue_stage = [&](int kt, int s) {
        uint32_t* As = smg + (size_t)s * 2 * 128 * GSAS;
        uint32_t* Bs = As + 128 * GSAS;
        #pragma unroll
        for (int rep = 0; rep < 2; rep++) {
            int row = rep * 64 + lrow;
            cpa16(&As[row * GSAS + lch * 4], gA + (size_t)(bm + row) * KDIM + kt * 32 + lch * 8);
            cpa16(&Bs[row * GSAS + lch * 4], gB + (size_t)(bn + row) * KDIM + kt * 32 + lch * 8);
        }
        CP_COMMIT;
    };

    #pragma unroll
    for (int s = 0; s < GSTAGES - 1; s++) issue_stage(s, s);

    float acc[4][4][4] = {};

    #pragma unroll 1
    for (int kt = 0; kt < KT; kt++) {
        if (kt < KT - 2) { CP_WAIT2; } else { CP_WAIT0; }
        __syncthreads();

        const uint32_t* As = smg + (size_t)(kt % GSTAGES) * 2 * 128 * GSAS;
        const uint32_t* Bs = As + 128 * GSAS;

        #pragma unroll
        for (int ks = 0; ks < 2; ks++) {
            const int kb = ks * 8;
            uint32_t af[4][4], bfr[4][2];
            #pragma unroll
            for (int i = 0; i < 4; i++) {
                const int rm = warpM * 64 + i * 16;
                af[i][0] = As[(rm + g) * GSAS + kb + tg];
                af[i][1] = As[(rm + g + 8) * GSAS + kb + tg];
                af[i][2] = As[(rm + g) * GSAS + kb + tg + 4];
                af[i][3] = As[(rm + g + 8) * GSAS + kb + tg + 4];
            }
            #pragma unroll
            for (int j = 0; j < 4; j++) {
                const int cn = warpN * 32 + j * 8;
                bfr[j][0] = Bs[(cn + g) * GSAS + kb + tg];
                bfr[j][1] = Bs[(cn + g) * GSAS + kb + tg + 4];
            }
            #pragma unroll
            for (int i = 0; i < 4; i++)
                #pragma unroll
                for (int j = 0; j < 4; j++)
                    mma_f16(acc[i][j], af[i], bfr[j]);
        }

        if (kt + GSTAGES - 1 < KT) issue_stage(kt + GSTAGES - 1, (kt + GSTAGES - 1) % GSTAGES);
    }

    #pragma unroll
    for (int i = 0; i < 4; i++) {
        const int rm = bm + warpM * 64 + i * 16;
        const int r0 = rm + g, r1 = rm + g + 8;
        #pragma unroll
        for (int j = 0; j < 4; j++) {
            const int n0 = bn + warpN * 32 + j * 8;
            const int nc = n0 + 2 * tg;
            float c0 = acc[i][j][0] + bias[nc], c1 = acc[i][j][1] + bias[nc + 1];
            float c2 = acc[i][j][2] + bias[nc], c3 = acc[i][j][3] + bias[nc + 1];
            if (MODE == 0) {
                const int h = n0 / (3 * HD_);
                const int which = (n0 % (3 * HD_)) / HD_;
                const int d = (n0 % HD_) + 2 * tg;
                const int bb = r0 >> 11;
                const int ss0 = r0 & (S_ - 1), ss1 = r1 & (S_ - 1);
                if (which == 0) {       // q: pre-scale so exp(s/64) = exp2(q'.k)
                    size_t base = (((size_t)bb * H_ + h) * S_) * HD_ + d;
                    *reinterpret_cast<__half2*>(g_q + base + (size_t)ss0 * HD_) =
                        __floats2half2_rn(c0 * QSC, c1 * QSC);
                    *reinterpret_cast<__half2*>(g_q + base + (size_t)ss1 * HD_) =
                        __floats2half2_rn(c2 * QSC, c3 * QSC);
                } else if (which == 1) {
                    size_t base = (((size_t)bb * H_ + h) * S_) * HD_ + d;
                    *reinterpret_cast<__half2*>(g_k + base + (size_t)ss0 * HD_) = __floats2half2_rn(c0, c1);
                    *reinterpret_cast<__half2*>(g_k + base + (size_t)ss1 * HD_) = __floats2half2_rn(c2, c3);
                } else {
                    size_t base = ((size_t)bb * H_ + h) * HD_;
                    g_vt[(base + d) * S_ + ss0]     = __float2half_rn(c0);
                    g_vt[(base + d + 1) * S_ + ss0] = __float2half_rn(c1);
                    g_vt[(base + d) * S_ + ss1]     = __float2half_rn(c2);
                    g_vt[(base + d + 1) * S_ + ss1] = __float2half_rn(c3);
                }
            } else {
                float* outp = pC ? pC : g_out_scratch;
                *reinterpret_cast<float2*>(outp + (size_t)r0 * D_ + nc) = make_float2(c0, c1);
                *reinterpret_cast<float2*>(outp + (size_t)r1 * D_ + nc) = make_float2(c2, c3);
            }
        }
    }
}

// ============================================================================
// Fused attention (round-12 math, KTILE=64 for 3 CTAs/SM occupancy).
// FIX vs round 14: load_v now loads the FULL 128B V^T row (8 chunks), matching
// the 32 k-words PV consumes. (Round 14 loaded 4 chunks -> NaN from
// uninitialized smem.)
// Smem 54KB: Qs[128][36], Ks[2][64][36], Vs[2][64][36] -> 3 CTAs/SM.
// ============================================================================
#define QSTR 36
#define KSTR 36
#define VSTR 36
#define KTILE 64
#define NKT (S_ / KTILE)                   // 32
#define KS_OFF (128 * QSTR)
#define VS_OFF (KS_OFF + 2 * KTILE * KSTR)
#define FA_SMEM ((128*QSTR + 2*KTILE*KSTR + 2*64*VSTR) * 4)   // 55296 B

__global__ __launch_bounds__(256, 3)
void fused_attn(float* __restrict__ attn_ext) {
    extern __shared__ uint32_t sm[];
    uint32_t* Qs = sm;                     // 128 x 36
    uint32_t* Ks = sm + KS_OFF;            // 2 x 64 x 36
    uint32_t* Vs = sm + VS_OFF;            // 2 x 64 x 36

    const int tid = threadIdx.x;
    const int wid = tid >> 5, lane = tid & 31;
    const int g = lane >> 2, tg = lane & 3;
    const int wm = wid * 16;               // warp's 16 q-rows
    const int bm = blockIdx.x * 128;
    const int bh = blockIdx.y;

    const __half* gQ  = g_q  + (size_t)bh * S_ * HD_ + (size_t)bm * HD_;
    const __half* gK  = g_k  + (size_t)bh * S_ * HD_;
    const __half* gVt = g_vt + (size_t)bh * HD_ * S_;
    float* attnp = (attn_ext ? attn_ext : g_attn_scratch) + (size_t)bh * S_ * S_;

    auto load_q = [&]() {
        #pragma unroll
        for (int rep = 0; rep < 4; rep++) {
            int idx = rep * 256 + tid, row = idx >> 3, ch = idx & 7;
            cpa16(&Qs[row * QSTR + ch * 4], gQ + (size_t)row * HD_ + ch * 8);
        }
    };
    // K tile: 64 rows x 64 fp16 (128B/row = 8 chunks) -> 512 cpa16
    auto load_k = [&](int kt, int b) {
        const __half* base = gK + (size_t)kt * KTILE * HD_;
        #pragma unroll
        for (int rep = 0; rep < 2; rep++) {
            int idx = rep * 256 + tid, row = idx >> 3, ch = idx & 7;
            cpa16(&Ks[b * KTILE * KSTR + row * KSTR + ch * 4], base + (size_t)row * HD_ + ch * 8);
        }
    };
    // V^T tile: 64 d-rows x 64 s = 128B/row = 8 chunks -> 512 cpa16 (FIXED)
    auto load_v = [&](int kt, int b) {
        const __half* base = gVt + (size_t)kt * KTILE;
        #pragma unroll
        for (int rep = 0; rep < 2; rep++) {
            int idx = rep * 256 + tid, row = idx >> 3, ch = idx & 7;
            cpa16(&Vs[b * 64 * VSTR + row * VSTR + ch * 4], base + (size_t)row * S_ + ch * 8);
        }
    };

    // S(16x64) = Q'_warp @ K^T over 8 n8 tiles
    auto compute_S = [&](const uint32_t* Kb, float sacc[8][4]) {
        #pragma unroll
        for (int j = 0; j < 8; j++)
            #pragma unroll
            for (int e = 0; e < 4; e++) sacc[j][e] = 0.0f;
        #pragma unroll
        for (int ks = 0; ks < 4; ks++) {
            const int kb = ks * 8;
            uint32_t af[4];
            af[0] = Qs[(wm + g) * QSTR + kb + tg];
            af[1] = Qs[(wm + g + 8) * QSTR + kb + tg];
            af[2] = Qs[(wm + g) * QSTR + kb + tg + 4];
            af[3] = Qs[(wm + g + 8) * QSTR + kb + tg + 4];
            #pragma unroll
            for (int j = 0; j < 8; j++) {
                uint32_t bf[2];
                bf[0] = Kb[(8 * j + g) * KSTR + kb + tg];
                bf[1] = Kb[(8 * j + g) * KSTR + kb + tg + 4];
                mma_f16(sacc[j], af, bf);
            }
        }
    };

    // ---- prologue ----
    load_q();
    load_k(0, 0);
    CP_COMMIT;
    CP_WAIT0;
    __syncthreads();

    // ================= pass 1: row sums of exp2 (registers only) ============
    float lp0 = 0.0f, lp1 = 0.0f;
    int b = 0;
    #pragma unroll 1
    for (int kt = 0; kt < NKT; kt++) {
        if (kt < NKT - 1) { load_k(kt + 1, b ^ 1); CP_COMMIT; }
        float sacc[8][4];
        compute_S(Ks + b * KTILE * KSTR, sacc);
        #pragma unroll
        for (int j = 0; j < 8; j++) {
            lp0 += ex2f(sacc[j][0]) + ex2f(sacc[j][1]);
            lp1 += ex2f(sacc[j][2]) + ex2f(sacc[j][3]);
        }
        if (kt < NKT - 1) { CP_WAIT0; __syncthreads(); b ^= 1; }
    }
    lp0 += __shfl_xor_sync(0xffffffff, lp0, 1);
    lp0 += __shfl_xor_sync(0xffffffff, lp0, 2);
    lp1 += __shfl_xor_sync(0xffffffff, lp1, 1);
    lp1 += __shfl_xor_sync(0xffffffff, lp1, 2);
    const float li0 = 1.0f / lp0;          // row wm+g
    const float li1 = 1.0f / lp1;          // row wm+g+8

    // ================= pass 2: attn write + O accumulation =================
    __syncthreads();                       // all warps done with pass-1 buffers
    load_k(0, 0); load_v(0, 0);
    CP_COMMIT;
    CP_WAIT0;
    __syncthreads();

    float oacc[8][4] = {};
    b = 0;
    #pragma unroll 1
    for (int kt = 0; kt < NKT; kt++) {
        if (kt < NKT - 1) { load_k(kt + 1, b ^ 1); load_v(kt + 1, b ^ 1); CP_COMMIT; }
        const uint32_t* Kb = Ks + b * KTILE * KSTR;
        const uint32_t* Vb = Vs + b * 64 * VSTR;
        float* arow0 = attnp + (size_t)(bm + wm + g) * S_ + kt * KTILE;
        float* arow1 = attnp + (size_t)(bm + wm + g + 8) * S_ + kt * KTILE;

        float sacc[8][4];
        compute_S(Kb, sacc);

        uint32_t paf[4][4];
        #pragma unroll
        for (int jj = 0; jj < 8; jj++) {
            const int col = jj * 8 + 2 * tg;
            float p0 = ex2f(sacc[jj][0]) * li0;
            float p1 = ex2f(sacc[jj][1]) * li0;
            float p2 = ex2f(sacc[jj][2]) * li1;
            float p3 = ex2f(sacc[jj][3]) * li1;
            stg_cs_v2(arow0 + col, p0, p1);
            stg_cs_v2(arow1 + col, p2, p3);
            paf[jj >> 1][(jj & 1) * 2 + 0] = h2u(__floats2half2_rn(p0, p1));
            paf[jj >> 1][(jj & 1) * 2 + 1] = h2u(__floats2half2_rn(p2, p3));
        }
        // O += P @ V (4 k16 chunks; V^T words 0..31 all loaded)
        #pragma unroll
        for (int ks = 0; ks < 4; ks++) {
            const int kb = ks * 8;
            #pragma unroll
            for (int jn = 0; jn < 8; jn++) {
                uint32_t bf[2];
                bf[0] = Vb[(8 * jn + g) * VSTR + kb + tg];
                bf[1] = Vb[(8 * jn + g) * VSTR + kb + tg + 4];
                mma_f16(oacc[jn], paf[ks], bf);
            }
        }
        if (kt < NKT - 1) { CP_WAIT0; __syncthreads(); b ^= 1; }
    }

    // ---- epilogue: O (16x64 per warp) -> g_vals fp16 ----
    const int bb = bh >> 4, h = bh & 15;
    __half* vbase = g_vals + (size_t)bb * S_ * E_ + (size_t)h * HD_;
    const int r0 = bm + wm + g, r1 = r0 + 8;
    #pragma unroll
    for (int jn = 0; jn < 8; jn++) {
        const int cn = 8 * jn + 2 * tg;
        *reinterpret_cast<__half2*>(vbase + (size_t)r0 * E_ + cn) =
            __floats2half2_rn(oacc[jn][0], oacc[jn][1]);
        *reinterpret_cast<__half2*>(vbase + (size_t)r1 * E_ + cn) =
            __floats2half2_rn(oacc[jn][2], oacc[jn][3]);
    }
}

// ============================================================================
// Launch. Inputs: x, w_qkv, b_qkv, w_out, b_out.
// ============================================================================
extern "C" void kernel_launch(void* const* d_in, const int* in_sizes, int n_in,
                              void* d_out, int out_size) {
    const float* x     = (const float*)d_in[0];
    const float* w_qkv = (const float*)d_in[1];
    const float* b_qkv = (const float*)d_in[2];
    const float* w_out = (const float*)d_in[3];
    const float* b_out = (const float*)d_in[4];
    float* dout = (float*)d_out;

    const long long OUTN  = (long long)MTOT * D_;
    const long long ATTNN = (long long)BHN * S_ * S_;
    float* out_ext  = nullptr;
    float* attn_ext = nullptr;
    const long long osz = (long long)out_size;
    if (osz >= OUTN + ATTNN) { out_ext = dout; attn_ext = dout + OUTN; }
    else if (osz == ATTNN)   { attn_ext = dout; }
    else                     { out_ext = dout; }

    cudaFuncSetAttribute(fused_attn, cudaFuncAttributeMaxDynamicSharedMemorySize, FA_SMEM);
    cudaFuncSetAttribute(mma_gemm<0>, cudaFuncAttributeMaxDynamicSharedMemorySize, GEMM_SMEM);
    cudaFuncSetAttribute(mma_gemm<3>, cudaFuncAttributeMaxDynamicSharedMemorySize, GEMM_SMEM);

    const long long CVT_N = (long long)MTOT * D_ + (long long)NQKV * D_ + (long long)D_ * E_;
    dim3 t(256);
    cvt_all<<<(unsigned)((CVT_N / 8 + 255) / 256), t>>>(x, w_qkv, w_out);

    mma_gemm<0><<<dim3(NQKV / 128, MTOT / 128), t, GEMM_SMEM>>>(b_qkv, nullptr);
    fused_attn<<<dim3(S_ / 128, BHN), t, FA_SMEM>>>(attn_ext);
    mma_gemm<3><<<dim3(D_ / 128, MTOT / 128), t, GEMM_SMEM>>>(b_out, out_ext);
}

// round 16
// speedup vs baseline: 1.3230x; 1.0856x over previous
#include <cuda_runtime.h>
#include <cuda_fp16.h>
#include <cstdint>

// Problem dims (fixed by reference)
#define B_   2
#define S_   2048
#define D_   1024
#define E_   1024
#define H_   16
#define HD_  64
#define MTOT (B_*S_)        // 4096
#define NQKV (3*E_)         // 3072
#define BHN  (B_*H_)        // 32

// log2(e)/64 folded into q so exp(s/64) == exp2(q'.k)
#define QSC 0.0225421246528f

// ---- static device scratch (no allocations allowed) ----
__device__ __align__(256) __half g_q[(size_t)BHN * S_ * HD_];     // [bh][s][d], pre-scaled by QSC
__device__ __align__(256) __half g_k[(size_t)BHN * S_ * HD_];     // [bh][s][d]
__device__ __align__(256) __half g_vt[(size_t)BHN * HD_ * S_];    // [bh][d][s]  (transposed)
__device__ __align__(256) __half g_vals[(size_t)MTOT * E_];       // O, fp16
__device__ __align__(256) __half g_x_h[(size_t)MTOT * D_];
__device__ __align__(256) __half g_wqkv_h[(size_t)NQKV * D_];
__device__ __align__(256) __half g_wout_h[(size_t)D_ * E_];
__device__ __align__(256) float  g_out_scratch[(size_t)MTOT * D_];
__device__ __align__(256) float  g_attn_scratch[(size_t)BHN * S_ * S_];

__device__ __forceinline__ uint32_t h2u(__half2 h) { return *reinterpret_cast<uint32_t*>(&h); }

__device__ __forceinline__ float ex2f(float x) {
    float y;
    asm("ex2.approx.f32 %0, %1;" : "=f"(y) : "f"(x));
    return y;
}

__device__ __forceinline__ void mma_f16(float c[4], const uint32_t a[4], const uint32_t b[2]) {
    asm volatile(
        "mma.sync.aligned.m16n8k16.row.col.f32.f16.f16.f32 "
        "{%0,%1,%2,%3}, {%4,%5,%6,%7}, {%8,%9}, {%0,%1,%2,%3};\n"
        : "+f"(c[0]), "+f"(c[1]), "+f"(c[2]), "+f"(c[3])
        : "r"(a[0]), "r"(a[1]), "r"(a[2]), "r"(a[3]), "r"(b[0]), "r"(b[1]));
}

__device__ __forceinline__ void cpa16(void* s, const void* g) {
    uint32_t sa = (uint32_t)__cvta_generic_to_shared(s);
    asm volatile("cp.async.cg.shared.global [%0], [%1], 16;" :: "r"(sa), "l"(g));
}
#define CP_COMMIT asm volatile("cp.async.commit_group;")
#define CP_WAIT0  asm volatile("cp.async.wait_group 0;")
#define CP_WAIT2  asm volatile("cp.async.wait_group 2;")

__device__ __forceinline__ void stg_cs_v2(float* p, float a, float b) {
    asm volatile("st.global.cs.v2.f32 [%0], {%1,%2};" :: "l"(p), "f"(a), "f"(b));
}

// ============================================================================
// fp32 -> fp16 conversion for x, w_qkv, w_out in ONE launch (8 elems/thread)
// ============================================================================
__global__ void cvt_all(const float* __restrict__ x, const float* __restrict__ wq,
                        const float* __restrict__ wo) {
    const long long N1 = (long long)MTOT * D_;
    const long long N2 = N1 + (long long)NQKV * D_;
    const long long N3 = N2 + (long long)D_ * E_;
    long long i = ((long long)blockIdx.x * blockDim.x + threadIdx.x) * 8;
    if (i >= N3) return;
    const float* in;
    __half* out;
    long long off;
    if (i < N1)      { in = x;  out = g_x_h;    off = i; }
    else if (i < N2) { in = wq; out = g_wqkv_h; off = i - N1; }
    else             { in = wo; out = g_wout_h; off = i - N2; }
    float4 a = *reinterpret_cast<const float4*>(in + off);
    float4 b = *reinterpret_cast<const float4*>(in + off + 4);
    uint4 u;
    u.x = h2u(__floats2half2_rn(a.x, a.y));
    u.y = h2u(__floats2half2_rn(a.z, a.w));
    u.z = h2u(__floats2half2_rn(b.x, b.y));
    u.w = h2u(__floats2half2_rn(b.z, b.w));
    *reinterpret_cast<uint4*>(out + off) = u;
}

// ============================================================================
// Dense GEMMs, fp16 mma m16n8k16, fp32 accum, 4-stage cp.async pipeline.
// MODE 0: qkv — +bias; q scaled by QSC; q/k row-major fp16; v transposed fp16.
// MODE 3: proj — +bias -> out (fp32)
// ============================================================================
#define GSTAGES 4
#define GSAS 20
#define GEMM_SMEM (GSTAGES * 2 * 128 * GSAS * 4)

template<int MODE>
__global__ __launch_bounds__(256)
void mma_gemm(const float* __restrict__ bias, float* __restrict__ pC) {
    constexpr int KDIM = 1024;
    constexpr int KT = KDIM / 32;

    extern __shared__ uint32_t smg[];

    const int tid = threadIdx.x;
    const int wid = tid >> 5, lane = tid & 31;
    const int g = lane >> 2, tg = lane & 3;
    const int warpM = wid / 4, warpN = wid % 4;
    const int bm = blockIdx.y * 128;
    const int bn = blockIdx.x * 128;

    const __half* gA = (MODE == 0) ? g_x_h : g_vals;
    const __half* gB = (MODE == 0) ? g_wqkv_h : g_wout_h;

    const int lrow = tid >> 2, lch = tid & 3;

    auto issue_stage = [&](int kt, int s) {
        uint32_t* As = smg + (size_t)s * 2 * 128 * GSAS;
        uint32_t* Bs = As + 128 * GSAS;
        #pragma unroll
        for (int rep = 0; rep < 2; rep++) {
            int row = rep * 64 + lrow;
            cpa16(&As[row * GSAS + lch * 4], gA + (size_t)(bm + row) * KDIM + kt * 32 + lch * 8);
            cpa16(&Bs[row * GSAS + lch * 4], gB + (size_t)(bn + row) * KDIM + kt * 32 + lch * 8);
        }
        CP_COMMIT;
    };

    #pragma unroll
    for (int s = 0; s < GSTAGES - 1; s++) issue_stage(s, s);

    float acc[4][4][4] = {};

    #pragma unroll 1
    for (int kt = 0; kt < KT; kt++) {
        if (kt < KT - 2) { CP_WAIT2; } else { CP_WAIT0; }
        __syncthreads();

        const uint32_t* As = smg + (size_t)(kt % GSTAGES) * 2 * 128 * GSAS;
        const uint32_t* Bs = As + 128 * GSAS;

        #pragma unroll
        for (int ks = 0; ks < 2; ks++) {
            const int kb = ks * 8;
            uint32_t af[4][4], bfr[4][2];
            #pragma unroll
            for (int i = 0; i < 4; i++) {
                const int rm = warpM * 64 + i * 16;
                af[i][0] = As[(rm + g) * GSAS + kb + tg];
                af[i][1] = As[(rm + g + 8) * GSAS + kb + tg];
                af[i][2] = As[(rm + g) * GSAS + kb + tg + 4];
                af[i][3] = As[(rm + g + 8) * GSAS + kb + tg + 4];
            }
            #pragma unroll
            for (int j = 0; j < 4; j++) {
                const int cn = warpN * 32 + j * 8;
                bfr[j][0] = Bs[(cn + g) * GSAS + kb + tg];
                bfr[j][1] = Bs[(cn + g) * GSAS + kb + tg + 4];
            }
            #pragma unroll
            for (int i = 0; i < 4; i++)
                #pragma unroll
                for (int j = 0; j < 4; j++)
                    mma_f16(acc[i][j], af[i], bfr[j]);
        }

        if (kt + GSTAGES - 1 < KT) issue_stage(kt + GSTAGES - 1, (kt + GSTAGES - 1) % GSTAGES);
    }

    #pragma unroll
    for (int i = 0; i < 4; i++) {
        const int rm = bm + warpM * 64 + i * 16;
        const int r0 = rm + g, r1 = rm + g + 8;
        #pragma unroll
        for (int j = 0; j < 4; j++) {
            const int n0 = bn + warpN * 32 + j * 8;
            const int nc = n0 + 2 * tg;
            float c0 = acc[i][j][0] + bias[nc], c1 = acc[i][j][1] + bias[nc + 1];
            float c2 = acc[i][j][2] + bias[nc], c3 = acc[i][j][3] + bias[nc + 1];
            if (MODE == 0) {
                const int h = n0 / (3 * HD_);
                const int which = (n0 % (3 * HD_)) / HD_;
                const int d = (n0 % HD_) + 2 * tg;
                const int bb = r0 >> 11;
                const int ss0 = r0 & (S_ - 1), ss1 = r1 & (S_ - 1);
                if (which == 0) {       // q: pre-scale so exp(s/64) = exp2(q'.k)
                    size_t base = (((size_t)bb * H_ + h) * S_) * HD_ + d;
                    *reinterpret_cast<__half2*>(g_q + base + (size_t)ss0 * HD_) =
                        __floats2half2_rn(c0 * QSC, c1 * QSC);
                    *reinterpret_cast<__half2*>(g_q + base + (size_t)ss1 * HD_) =
                        __floats2half2_rn(c2 * QSC, c3 * QSC);
                } else if (which == 1) {
                    size_t base = (((size_t)bb * H_ + h) * S_) * HD_ + d;
                    *reinterpret_cast<__half2*>(g_k + base + (size_t)ss0 * HD_) = __floats2half2_rn(c0, c1);
                    *reinterpret_cast<__half2*>(g_k + base + (size_t)ss1 * HD_) = __floats2half2_rn(c2, c3);
                } else {
                    size_t base = ((size_t)bb * H_ + h) * HD_;
                    g_vt[(base + d) * S_ + ss0]     = __float2half_rn(c0);
                    g_vt[(base + d + 1) * S_ + ss0] = __float2half_rn(c1);
                    g_vt[(base + d) * S_ + ss1]     = __float2half_rn(c2);
                    g_vt[(base + d + 1) * S_ + ss1] = __float2half_rn(c3);
                }
            } else {
                float* outp = pC ? pC : g_out_scratch;
                *reinterpret_cast<float2*>(outp + (size_t)r0 * D_ + nc) = make_float2(c0, c1);
                *reinterpret_cast<float2*>(outp + (size_t)r1 * D_ + nc) = make_float2(c2, c3);
            }
        }
    }
}

// ============================================================================
// Fused attention (round-12 proven config, 394.9us):
//   pass 1: l[row] = sum exp2(q'.k)      (QK mma + MUFU only, register sums)
//   pass 2: recompute S in 64-col halves; per half: exp2 -> attn write (st.cs)
//           -> pack fp16 PV A-frags in regs -> PV mma. One sync per tile.
// Smem 88KB: Qs[128][36], Ks[2][128][36], Vs[2][64][68] -> 2 CTAs/SM.
// ============================================================================
#define QSTR 36
#define KSTR 36
#define VSTR 68
#define NKT (S_ / 128)                     // 16
#define KS_OFF (128 * QSTR)
#define VS_OFF (KS_OFF + 2 * 128 * KSTR)
#define FA_SMEM ((128*QSTR + 2*128*KSTR + 2*64*VSTR) * 4)   // 90112 B

__global__ __launch_bounds__(256, 2)
void fused_attn(float* __restrict__ attn_ext) {
    extern __shared__ uint32_t sm[];
    uint32_t* Qs = sm;                     // 128 x 36
    uint32_t* Ks = sm + KS_OFF;            // 2 x 128 x 36
    uint32_t* Vs = sm + VS_OFF;            // 2 x 64 x 68

    const int tid = threadIdx.x;
    const int wid = tid >> 5, lane = tid & 31;
    const int g = lane >> 2, tg = lane & 3;
    const int wm = wid * 16;               // warp's 16 q-rows
    const int bm = blockIdx.x * 128;
    const int bh = blockIdx.y;

    const __half* gQ  = g_q  + (size_t)bh * S_ * HD_ + (size_t)bm * HD_;
    const __half* gK  = g_k  + (size_t)bh * S_ * HD_;
    const __half* gVt = g_vt + (size_t)bh * HD_ * S_;
    float* attnp = (attn_ext ? attn_ext : g_attn_scratch) + (size_t)bh * S_ * S_;

    auto load_q = [&]() {
        #pragma unroll
        for (int rep = 0; rep < 4; rep++) {
            int idx = rep * 256 + tid, row = idx >> 3, ch = idx & 7;
            cpa16(&Qs[row * QSTR + ch * 4], gQ + (size_t)row * HD_ + ch * 8);
        }
    };
    auto load_k = [&](int kt, int b) {
        const __half* base = gK + (size_t)kt * 128 * HD_;
        #pragma unroll
        for (int rep = 0; rep < 4; rep++) {
            int idx = rep * 256 + tid, row = idx >> 3, ch = idx & 7;
            cpa16(&Ks[b * 128 * KSTR + row * KSTR + ch * 4], base + (size_t)row * HD_ + ch * 8);
        }
    };
    auto load_v = [&](int kt, int b) {   // V^T tile: 64 d-rows x 128 s-cols
        const __half* base = gVt + (size_t)kt * 128;
        #pragma unroll
        for (int rep = 0; rep < 4; rep++) {
            int idx = rep * 256 + tid, row = idx >> 4, ch = idx & 15;
            cpa16(&Vs[b * 64 * VSTR + row * VSTR + ch * 4], base + (size_t)row * S_ + ch * 8);
        }
    };

    // S(16x64 half) = Q'_warp @ K^T over n8 tiles [jbase, jbase+8)
    auto compute_S_half = [&](const uint32_t* Kb, float sacc[8][4], int jbase) {
        #pragma unroll
        for (int j = 0; j < 8; j++)
            #pragma unroll
            for (int e = 0; e < 4; e++) sacc[j][e] = 0.0f;
        #pragma unroll
        for (int ks = 0; ks < 4; ks++) {
            const int kb = ks * 8;
            uint32_t af[4];
            af[0] = Qs[(wm + g) * QSTR + kb + tg];
            af[1] = Qs[(wm + g + 8) * QSTR + kb + tg];
            af[2] = Qs[(wm + g) * QSTR + kb + tg + 4];
            af[3] = Qs[(wm + g + 8) * QSTR + kb + tg + 4];
            #pragma unroll
            for (int j = 0; j < 8; j++) {
                uint32_t bf[2];
                bf[0] = Kb[(8 * (jbase + j) + g) * KSTR + kb + tg];
                bf[1] = Kb[(8 * (jbase + j) + g) * KSTR + kb + tg + 4];
                mma_f16(sacc[j], af, bf);
            }
        }
    };

    // ---- prologue ----
    load_q();
    load_k(0, 0);
    CP_COMMIT;
    CP_WAIT0;
    __syncthreads();

    // ================= pass 1: row sums of exp2 (registers only) ============
    float lp0 = 0.0f, lp1 = 0.0f;
    int b = 0;
    #pragma unroll 1
    for (int kt = 0; kt < NKT; kt++) {
        if (kt < NKT - 1) { load_k(kt + 1, b ^ 1); CP_COMMIT; }
        #pragma unroll
        for (int half = 0; half < 2; half++) {
            float sacc[8][4];
            compute_S_half(Ks + b * 128 * KSTR, sacc, half * 8);
            #pragma unroll
            for (int j = 0; j < 8; j++) {
                lp0 += ex2f(sacc[j][0]) + ex2f(sacc[j][1]);
                lp1 += ex2f(sacc[j][2]) + ex2f(sacc[j][3]);
            }
        }
        if (kt < NKT - 1) { CP_WAIT0; __syncthreads(); b ^= 1; }
    }
    lp0 += __shfl_xor_sync(0xffffffff, lp0, 1);
    lp0 += __shfl_xor_sync(0xffffffff, lp0, 2);
    lp1 += __shfl_xor_sync(0xffffffff, lp1, 1);
    lp1 += __shfl_xor_sync(0xffffffff, lp1, 2);
    const float li0 = 1.0f / lp0;          // row wm+g
    const float li1 = 1.0f / lp1;          // row wm+g+8

    // ================= pass 2: attn write + O accumulation =================
    load_k(0, 0); load_v(0, 0);
    CP_COMMIT;
    CP_WAIT0;
    __syncthreads();

    float oacc[8][4] = {};
    b = 0;
    #pragma unroll 1
    for (int kt = 0; kt < NKT; kt++) {
        if (kt < NKT - 1) { load_k(kt + 1, b ^ 1); load_v(kt + 1, b ^ 1); CP_COMMIT; }
        const uint32_t* Kb = Ks + b * 128 * KSTR;
        const uint32_t* Vb = Vs + b * 64 * VSTR;
        float* arow0 = attnp + (size_t)(bm + wm + g) * S_ + kt * 128;
        float* arow1 = attnp + (size_t)(bm + wm + g + 8) * S_ + kt * 128;

        #pragma unroll
        for (int half = 0; half < 2; half++) {
            float sacc[8][4];
            compute_S_half(Kb, sacc, half * 8);

            uint32_t paf[4][4];
            #pragma unroll
            for (int jj = 0; jj < 8; jj++) {
                const int col = (half * 8 + jj) * 8 + 2 * tg;
                float p0 = ex2f(sacc[jj][0]) * li0;
                float p1 = ex2f(sacc[jj][1]) * li0;
                float p2 = ex2f(sacc[jj][2]) * li1;
                float p3 = ex2f(sacc[jj][3]) * li1;
                stg_cs_v2(arow0 + col, p0, p1);
                stg_cs_v2(arow1 + col, p2, p3);
                paf[jj >> 1][(jj & 1) * 2 + 0] = h2u(__floats2half2_rn(p0, p1));
                paf[jj >> 1][(jj & 1) * 2 + 1] = h2u(__floats2half2_rn(p2, p3));
            }
            // O += P_half @ V (k16 steps half*4 .. half*4+3)
            #pragma unroll
            for (int ks = 0; ks < 4; ks++) {
                const int kb = (half * 4 + ks) * 8;
                #pragma unroll
                for (int jn = 0; jn < 8; jn++) {
                    uint32_t bf[2];
                    bf[0] = Vb[(8 * jn + g) * VSTR + kb + tg];
                    bf[1] = Vb[(8 * jn + g) * VSTR + kb + tg + 4];
                    mma_f16(oacc[jn], paf[ks], bf);
                }
            }
        }
        if (kt < NKT - 1) { CP_WAIT0; __syncthreads(); b ^= 1; }
    }

    // ---- epilogue: O (16x64 per warp) -> g_vals fp16 ----
    const int bb = bh >> 4, h = bh & 15;
    __half* vbase = g_vals + (size_t)bb * S_ * E_ + (size_t)h * HD_;
    const int r0 = bm + wm + g, r1 = r0 + 8;
    #pragma unroll
    for (int jn = 0; jn < 8; jn++) {
        const int cn = 8 * jn + 2 * tg;
        *reinterpret_cast<__half2*>(vbase + (size_t)r0 * E_ + cn) =
            __floats2half2_rn(oacc[jn][0], oacc[jn][1]);
        *reinterpret_cast<__half2*>(vbase + (size_t)r1 * E_ + cn) =
            __floats2half2_rn(oacc[jn][2], oacc[jn][3]);
    }
}

// ============================================================================
// Launch. Inputs: x, w_qkv, b_qkv, w_out, b_out.
// ============================================================================
extern "C" void kernel_launch(void* const* d_in, const int* in_sizes, int n_in,
                              void* d_out, int out_size) {
    const float* x     = (const float*)d_in[0];
    const float* w_qkv = (const float*)d_in[1];
    const float* b_qkv = (const float*)d_in[2];
    const float* w_out = (const float*)d_in[3];
    const float* b_out = (const float*)d_in[4];
    float* dout = (float*)d_out;

    const long long OUTN  = (long long)MTOT * D_;
    const long long ATTNN = (long long)BHN * S_ * S_;
    float* out_ext  = nullptr;
    float* attn_ext = nullptr;
    const long long osz = (long long)out_size;
    if (osz >= OUTN + ATTNN) { out_ext = dout; attn_ext = dout + OUTN; }
    else if (osz == ATTNN)   { attn_ext = dout; }
    else                     { out_ext = dout; }

    cudaFuncSetAttribute(fused_attn, cudaFuncAttributeMaxDynamicSharedMemorySize, FA_SMEM);
    cudaFuncSetAttribute(mma_gemm<0>, cudaFuncAttributeMaxDynamicSharedMemorySize, GEMM_SMEM);
    cudaFuncSetAttribute(mma_gemm<3>, cudaFuncAttributeMaxDynamicSharedMemorySize, GEMM_SMEM);

    const long long CVT_N = (long long)MTOT * D_ + (long long)NQKV * D_ + (long long)D_ * E_;
    dim3 t(256);
    cvt_all<<<(unsigned)((CVT_N / 8 + 255) / 256), t>>>(x, w_qkv, w_out);

    mma_gemm<0><<<dim3(NQKV / 128, MTOT / 128), t, GEMM_SMEM>>>(b_qkv, nullptr);
    fused_attn<<<dim3(S_ / 128, BHN), t, FA_SMEM>>>(attn_ext);
    mma_gemm<3><<<dim3(D_ / 128, MTOT / 128), t, GEMM_SMEM>>>(b_out, out_ext);
}

// round 17
// speedup vs baseline: 1.3360x; 1.0098x over previous
#include <cuda_runtime.h>
#include <cuda_fp16.h>
#include <cstdint>

// Problem dims (fixed by reference)
#define B_   2
#define S_   2048
#define D_   1024
#define E_   1024
#define H_   16
#define HD_  64
#define MTOT (B_*S_)        // 4096
#define NQKV (3*E_)         // 3072
#define BHN  (B_*H_)        // 32

// log2(e)/64 folded into q so exp(s/64) == exp2(q'.k)
#define QSC 0.0225421246528f

// ---- static device scratch (no allocations allowed) ----
__device__ __align__(256) __half g_q[(size_t)BHN * S_ * HD_];     // [bh][s][d], pre-scaled by QSC
__device__ __align__(256) __half g_k[(size_t)BHN * S_ * HD_];     // [bh][s][d]
__device__ __align__(256) __half g_vt[(size_t)BHN * HD_ * S_];    // [bh][d][s]  (transposed)
__device__ __align__(256) __half g_vals[(size_t)MTOT * E_];       // O, fp16
__device__ __align__(256) __half g_x_h[(size_t)MTOT * D_];
__device__ __align__(256) __half g_wqkv_h[(size_t)NQKV * D_];
__device__ __align__(256) __half g_wout_h[(size_t)D_ * E_];
__device__ __align__(256) float  g_out_scratch[(size_t)MTOT * D_];
__device__ __align__(256) float  g_attn_scratch[(size_t)BHN * S_ * S_];

__device__ __forceinline__ uint32_t h2u(__half2 h) { return *reinterpret_cast<uint32_t*>(&h); }

__device__ __forceinline__ float ex2f(float x) {
    float y;
    asm("ex2.approx.f32 %0, %1;" : "=f"(y) : "f"(x));
    return y;
}
// two exp2 in one MUFU op
__device__ __forceinline__ __half2 ex2h2(__half2 x) {
    uint32_t xi = *reinterpret_cast<uint32_t*>(&x), yi;
    asm("ex2.approx.f16x2 %0, %1;" : "=r"(yi) : "r"(xi));
    return *reinterpret_cast<__half2*>(&yi);
}

__device__ __forceinline__ void mma_f16(float c[4], const uint32_t a[4], const uint32_t b[2]) {
    asm volatile(
        "mma.sync.aligned.m16n8k16.row.col.f32.f16.f16.f32 "
        "{%0,%1,%2,%3}, {%4,%5,%6,%7}, {%8,%9}, {%0,%1,%2,%3};\n"
        : "+f"(c[0]), "+f"(c[1]), "+f"(c[2]), "+f"(c[3])
        : "r"(a[0]), "r"(a[1]), "r"(a[2]), "r"(a[3]), "r"(b[0]), "r"(b[1]));
}

__device__ __forceinline__ void cpa16(void* s, const void* g) {
    uint32_t sa = (uint32_t)__cvta_generic_to_shared(s);
    asm volatile("cp.async.cg.shared.global [%0], [%1], 16;" :: "r"(sa), "l"(g));
}
#define CP_COMMIT asm volatile("cp.async.commit_group;")
#define CP_WAIT0  asm volatile("cp.async.wait_group 0;")
#define CP_WAIT2  asm volatile("cp.async.wait_group 2;")

__device__ __forceinline__ void stg_cs_v2(float* p, float a, float b) {
    asm volatile("st.global.cs.v2.f32 [%0], {%1,%2};" :: "l"(p), "f"(a), "f"(b));
}

// ============================================================================
// fp32 -> fp16 conversion for x, w_qkv, w_out in ONE launch (8 elems/thread)
// ============================================================================
__global__ void cvt_all(const float* __restrict__ x, const float* __restrict__ wq,
                        const float* __restrict__ wo) {
    const long long N1 = (long long)MTOT * D_;
    const long long N2 = N1 + (long long)NQKV * D_;
    const long long N3 = N2 + (long long)D_ * E_;
    long long i = ((long long)blockIdx.x * blockDim.x + threadIdx.x) * 8;
    if (i >= N3) return;
    const float* in;
    __half* out;
    long long off;
    if (i < N1)      { in = x;  out = g_x_h;    off = i; }
    else if (i < N2) { in = wq; out = g_wqkv_h; off = i - N1; }
    else             { in = wo; out = g_wout_h; off = i - N2; }
    float4 a = *reinterpret_cast<const float4*>(in + off);
    float4 b = *reinterpret_cast<const float4*>(in + off + 4);
    uint4 u;
    u.x = h2u(__floats2half2_rn(a.x, a.y));
    u.y = h2u(__floats2half2_rn(a.z, a.w));
    u.z = h2u(__floats2half2_rn(b.x, b.y));
    u.w = h2u(__floats2half2_rn(b.z, b.w));
    *reinterpret_cast<uint4*>(out + off) = u;
}

// ============================================================================
// Dense GEMMs, fp16 mma m16n8k16, fp32 accum, 4-stage cp.async pipeline.
// MODE 0: qkv — +bias; q scaled by QSC; q/k row-major fp16; v transposed fp16.
// MODE 3: proj — +bias -> out (fp32)
// ============================================================================
#define GSTAGES 4
#define GSAS 20
#define GEMM_SMEM (GSTAGES * 2 * 128 * GSAS * 4)

template<int MODE>
__global__ __launch_bounds__(256)
void mma_gemm(const float* __restrict__ bias, float* __restrict__ pC) {
    constexpr int KDIM = 1024;
    constexpr int KT = KDIM / 32;

    extern __shared__ uint32_t smg[];

    const int tid = threadIdx.x;
    const int wid = tid >> 5, lane = tid & 31;
    const int g = lane >> 2, tg = lane & 3;
    const int warpM = wid / 4, warpN = wid % 4;
    const int bm = blockIdx.y * 128;
    const int bn = blockIdx.x * 128;

    const __half* gA = (MODE == 0) ? g_x_h : g_vals;
    const __half* gB = (MODE == 0) ? g_wqkv_h : g_wout_h;

    const int lrow = tid >> 2, lch = tid & 3;

    auto issue_stage = [&](int kt, int s) {
        uint32_t* As = smg + (size_t)s * 2 * 128 * GSAS;
        uint32_t* Bs = As + 128 * GSAS;
        #pragma unroll
        for (int rep = 0; rep < 2; rep++) {
            int row = rep * 64 + lrow;
            cpa16(&As[row * GSAS + lch * 4], gA + (size_t)(bm + row) * KDIM + kt * 32 + lch * 8);
            cpa16(&Bs[row * GSAS + lch * 4], gB + (size_t)(bn + row) * KDIM + kt * 32 + lch * 8);
        }
        CP_COMMIT;
    };

    #pragma unroll
    for (int s = 0; s < GSTAGES - 1; s++) issue_stage(s, s);

    float acc[4][4][4] = {};

    #pragma unroll 1
    for (int kt = 0; kt < KT; kt++) {
        if (kt < KT - 2) { CP_WAIT2; } else { CP_WAIT0; }
        __syncthreads();

        const uint32_t* As = smg + (size_t)(kt % GSTAGES) * 2 * 128 * GSAS;
        const uint32_t* Bs = As + 128 * GSAS;

        #pragma unroll
        for (int ks = 0; ks < 2; ks++) {
            const int kb = ks * 8;
            uint32_t af[4][4], bfr[4][2];
            #pragma unroll
            for (int i = 0; i < 4; i++) {
                const int rm = warpM * 64 + i * 16;
                af[i][0] = As[(rm + g) * GSAS + kb + tg];
                af[i][1] = As[(rm + g + 8) * GSAS + kb + tg];
                af[i][2] = As[(rm + g) * GSAS + kb + tg + 4];
                af[i][3] = As[(rm + g + 8) * GSAS + kb + tg + 4];
            }
            #pragma unroll
            for (int j = 0; j < 4; j++) {
                const int cn = warpN * 32 + j * 8;
                bfr[j][0] = Bs[(cn + g) * GSAS + kb + tg];
                bfr[j][1] = Bs[(cn + g) * GSAS + kb + tg + 4];
            }
            #pragma unroll
            for (int i = 0; i < 4; i++)
                #pragma unroll
                for (int j = 0; j < 4; j++)
                    mma_f16(acc[i][j], af[i], bfr[j]);
        }

        if (kt + GSTAGES - 1 < KT) issue_stage(kt + GSTAGES - 1, (kt + GSTAGES - 1) % GSTAGES);
    }

    #pragma unroll
    for (int i = 0; i < 4; i++) {
        const int rm = bm + warpM * 64 + i * 16;
        const int r0 = rm + g, r1 = rm + g + 8;
        #pragma unroll
        for (int j = 0; j < 4; j++) {
            const int n0 = bn + warpN * 32 + j * 8;
            const int nc = n0 + 2 * tg;
            float c0 = acc[i][j][0] + bias[nc], c1 = acc[i][j][1] + bias[nc + 1];
            float c2 = acc[i][j][2] + bias[nc], c3 = acc[i][j][3] + bias[nc + 1];
            if (MODE == 0) {
                const int h = n0 / (3 * HD_);
                const int which = (n0 % (3 * HD_)) / HD_;
                const int d = (n0 % HD_) + 2 * tg;
                const int bb = r0 >> 11;
                const int ss0 = r0 & (S_ - 1), ss1 = r1 & (S_ - 1);
                if (which == 0) {       // q: pre-scale so exp(s/64) = exp2(q'.k)
                    size_t base = (((size_t)bb * H_ + h) * S_) * HD_ + d;
                    *reinterpret_cast<__half2*>(g_q + base + (size_t)ss0 * HD_) =
                        __floats2half2_rn(c0 * QSC, c1 * QSC);
                    *reinterpret_cast<__half2*>(g_q + base + (size_t)ss1 * HD_) =
                        __floats2half2_rn(c2 * QSC, c3 * QSC);
                } else if (which == 1) {
                    size_t base = (((size_t)bb * H_ + h) * S_) * HD_ + d;
                    *reinterpret_cast<__half2*>(g_k + base + (size_t)ss0 * HD_) = __floats2half2_rn(c0, c1);
                    *reinterpret_cast<__half2*>(g_k + base + (size_t)ss1 * HD_) = __floats2half2_rn(c2, c3);
                } else {
                    size_t base = ((size_t)bb * H_ + h) * HD_;
                    g_vt[(base + d) * S_ + ss0]     = __float2half_rn(c0);
                    g_vt[(base + d + 1) * S_ + ss0] = __float2half_rn(c1);
                    g_vt[(base + d) * S_ + ss1]     = __float2half_rn(c2);
                    g_vt[(base + d + 1) * S_ + ss1] = __float2half_rn(c3);
                }
            } else {
                float* outp = pC ? pC : g_out_scratch;
                *reinterpret_cast<float2*>(outp + (size_t)r0 * D_ + nc) = make_float2(c0, c1);
                *reinterpret_cast<float2*>(outp + (size_t)r1 * D_ + nc) = make_float2(c2, c3);
            }
        }
    }
}

// ============================================================================
// Fused attention (round-16 config + pass-1 f16x2 exp + early pass-2 prefetch):
//   pass 1: l[row] = sum exp2(q'.k) via ex2.approx.f16x2 (quarter MUFU issue),
//           HADD2 trees of 8 per half, fp32 inter-tile accumulation.
//   pass 2: unchanged fp32 exp path (attn precision preserved).
// Smem 88KB: Qs[128][36], Ks[2][128][36], Vs[2][64][68] -> 2 CTAs/SM.
// ============================================================================
#define QSTR 36
#define KSTR 36
#define VSTR 68
#define NKT (S_ / 128)                     // 16
#define KS_OFF (128 * QSTR)
#define VS_OFF (KS_OFF + 2 * 128 * KSTR)
#define FA_SMEM ((128*QSTR + 2*128*KSTR + 2*64*VSTR) * 4)   // 90112 B

__global__ __launch_bounds__(256, 2)
void fused_attn(float* __restrict__ attn_ext) {
    extern __shared__ uint32_t sm[];
    uint32_t* Qs = sm;                     // 128 x 36
    uint32_t* Ks = sm + KS_OFF;            // 2 x 128 x 36
    uint32_t* Vs = sm + VS_OFF;            // 2 x 64 x 68

    const int tid = threadIdx.x;
    const int wid = tid >> 5, lane = tid & 31;
    const int g = lane >> 2, tg = lane & 3;
    const int wm = wid * 16;               // warp's 16 q-rows
    const int bm = blockIdx.x * 128;
    const int bh = blockIdx.y;

    const __half* gQ  = g_q  + (size_t)bh * S_ * HD_ + (size_t)bm * HD_;
    const __half* gK  = g_k  + (size_t)bh * S_ * HD_;
    const __half* gVt = g_vt + (size_t)bh * HD_ * S_;
    float* attnp = (attn_ext ? attn_ext : g_attn_scratch) + (size_t)bh * S_ * S_;

    auto load_q = [&]() {
        #pragma unroll
        for (int rep = 0; rep < 4; rep++) {
            int idx = rep * 256 + tid, row = idx >> 3, ch = idx & 7;
            cpa16(&Qs[row * QSTR + ch * 4], gQ + (size_t)row * HD_ + ch * 8);
        }
    };
    auto load_k = [&](int kt, int b) {
        const __half* base = gK + (size_t)kt * 128 * HD_;
        #pragma unroll
        for (int rep = 0; rep < 4; rep++) {
            int idx = rep * 256 + tid, row = idx >> 3, ch = idx & 7;
            cpa16(&Ks[b * 128 * KSTR + row * KSTR + ch * 4], base + (size_t)row * HD_ + ch * 8);
        }
    };
    auto load_v = [&](int kt, int b) {   // V^T tile: 64 d-rows x 128 s-cols
        const __half* base = gVt + (size_t)kt * 128;
        #pragma unroll
        for (int rep = 0; rep < 4; rep++) {
            int idx = rep * 256 + tid, row = idx >> 4, ch = idx & 15;
            cpa16(&Vs[b * 64 * VSTR + row * VSTR + ch * 4], base + (size_t)row * S_ + ch * 8);
        }
    };

    // S(16x64 half) = Q'_warp @ K^T over n8 tiles [jbase, jbase+8)
    auto compute_S_half = [&](const uint32_t* Kb, float sacc[8][4], int jbase) {
        #pragma unroll
        for (int j = 0; j < 8; j++)
            #pragma unroll
            for (int e = 0; e < 4; e++) sacc[j][e] = 0.0f;
        #pragma unroll
        for (int ks = 0; ks < 4; ks++) {
            const int kb = ks * 8;
            uint32_t af[4];
            af[0] = Qs[(wm + g) * QSTR + kb + tg];
            af[1] = Qs[(wm + g + 8) * QSTR + kb + tg];
            af[2] = Qs[(wm + g) * QSTR + kb + tg + 4];
            af[3] = Qs[(wm + g + 8) * QSTR + kb + tg + 4];
            #pragma unroll
            for (int j = 0; j < 8; j++) {
                uint32_t bf[2];
                bf[0] = Kb[(8 * (jbase + j) + g) * KSTR + kb + tg];
                bf[1] = Kb[(8 * (jbase + j) + g) * KSTR + kb + tg + 4];
                mma_f16(sacc[j], af, bf);
            }
        }
    };

    // ---- prologue ----
    load_q();
    load_k(0, 0);
    CP_COMMIT;
    CP_WAIT0;
    __syncthreads();

    // ================= pass 1: row sums of exp2 (f16x2 MUFU) ================
    float lp0 = 0.0f, lp1 = 0.0f;
    int b = 0;
    #pragma unroll 1
    for (int kt = 0; kt < NKT; kt++) {
        if (kt < NKT - 1) { load_k(kt + 1, b ^ 1); CP_COMMIT; }
        #pragma unroll
        for (int half = 0; half < 2; half++) {
            float sacc[8][4];
            compute_S_half(Ks + b * 128 * KSTR, sacc, half * 8);
            __half2 a0 = __floats2half2_rn(0.0f, 0.0f);
            __half2 a1 = a0;
            #pragma unroll
            for (int j = 0; j < 8; j++) {
                a0 = __hadd2(a0, ex2h2(__floats2half2_rn(sacc[j][0], sacc[j][1])));
                a1 = __hadd2(a1, ex2h2(__floats2half2_rn(sacc[j][2], sacc[j][3])));
            }
            float2 f0 = __half22float2(a0);
            float2 f1 = __half22float2(a1);
            lp0 += f0.x + f0.y;
            lp1 += f1.x + f1.y;
        }
        if (kt < NKT - 1) { CP_WAIT0; __syncthreads(); b ^= 1; }
    }

    // prefetch pass-2 first tiles (buffer 0 is dead: last computed at kt=14,
    // fenced by the end-of-kt=14 sync; V buffers untouched in pass 1)
    load_k(0, 0); load_v(0, 0);
    CP_COMMIT;

    lp0 += __shfl_xor_sync(0xffffffff, lp0, 1);
    lp0 += __shfl_xor_sync(0xffffffff, lp0, 2);
    lp1 += __shfl_xor_sync(0xffffffff, lp1, 1);
    lp1 += __shfl_xor_sync(0xffffffff, lp1, 2);
    const float li0 = 1.0f / lp0;          // row wm+g
    const float li1 = 1.0f / lp1;          // row wm+g+8

    CP_WAIT0;
    __syncthreads();

    // ================= pass 2: attn write + O accumulation =================
    float oacc[8][4] = {};
    b = 0;
    #pragma unroll 1
    for (int kt = 0; kt < NKT; kt++) {
        if (kt < NKT - 1) { load_k(kt + 1, b ^ 1); load_v(kt + 1, b ^ 1); CP_COMMIT; }
        const uint32_t* Kb = Ks + b * 128 * KSTR;
        const uint32_t* Vb = Vs + b * 64 * VSTR;
        float* arow0 = attnp + (size_t)(bm + wm + g) * S_ + kt * 128;
        float* arow1 = attnp + (size_t)(bm + wm + g + 8) * S_ + kt * 128;

        #pragma unroll
        for (int half = 0; half < 2; half++) {
            float sacc[8][4];
            compute_S_half(Kb, sacc, half * 8);

            uint32_t paf[4][4];
            #pragma unroll
            for (int jj = 0; jj < 8; jj++) {
                const int col = (half * 8 + jj) * 8 + 2 * tg;
                float p0 = ex2f(sacc[jj][0]) * li0;
                float p1 = ex2f(sacc[jj][1]) * li0;
                float p2 = ex2f(sacc[jj][2]) * li1;
                float p3 = ex2f(sacc[jj][3]) * li1;
                stg_cs_v2(arow0 + col, p0, p1);
                stg_cs_v2(arow1 + col, p2, p3);
                paf[jj >> 1][(jj & 1) * 2 + 0] = h2u(__floats2half2_rn(p0, p1));
                paf[jj >> 1][(jj & 1) * 2 + 1] = h2u(__floats2half2_rn(p2, p3));
            }
            // O += P_half @ V (k16 steps half*4 .. half*4+3)
            #pragma unroll
            for (int ks = 0; ks < 4; ks++) {
                const int kb = (half * 4 + ks) * 8;
                #pragma unroll
                for (int jn = 0; jn < 8; jn++) {
                    uint32_t bf[2];
                    bf[0] = Vb[(8 * jn + g) * VSTR + kb + tg];
                    bf[1] = Vb[(8 * jn + g) * VSTR + kb + tg + 4];
                    mma_f16(oacc[jn], paf[ks], bf);
                }
            }
        }
        if (kt < NKT - 1) { CP_WAIT0; __syncthreads(); b ^= 1; }
    }

    // ---- epilogue: O (16x64 per warp) -> g_vals fp16 ----
    const int bb = bh >> 4, h = bh & 15;
    __half* vbase = g_vals + (size_t)bb * S_ * E_ + (size_t)h * HD_;
    const int r0 = bm + wm + g, r1 = r0 + 8;
    #pragma unroll
    for (int jn = 0; jn < 8; jn++) {
        const int cn = 8 * jn + 2 * tg;
        *reinterpret_cast<__half2*>(vbase + (size_t)r0 * E_ + cn) =
            __floats2half2_rn(oacc[jn][0], oacc[jn][1]);
        *reinterpret_cast<__half2*>(vbase + (size_t)r1 * E_ + cn) =
            __floats2half2_rn(oacc[jn][2], oacc[jn][3]);
    }
}

// ============================================================================
// Launch. Inputs: x, w_qkv, b_qkv, w_out, b_out.
// ============================================================================
extern "C" void kernel_launch(void* const* d_in, const int* in_sizes, int n_in,
                              void* d_out, int out_size) {
    const float* x     = (const float*)d_in[0];
    const float* w_qkv = (const float*)d_in[1];
    const float* b_qkv = (const float*)d_in[2];
    const float* w_out = (const float*)d_in[3];
    const float* b_out = (const float*)d_in[4];
    float* dout = (float*)d_out;

    const long long OUTN  = (long long)MTOT * D_;
    const long long ATTNN = (long long)BHN * S_ * S_;
    float* out_ext  = nullptr;
    float* attn_ext = nullptr;
    const long long osz = (long long)out_size;
    if (osz >= OUTN + ATTNN) { out_ext = dout; attn_ext = dout + OUTN; }
    else if (osz == ATTNN)   { attn_ext = dout; }
    else                     { out_ext = dout; }

    cudaFuncSetAttribute(fused_attn, cudaFuncAttributeMaxDynamicSharedMemorySize, FA_SMEM);
    cudaFuncSetAttribute(mma_gemm<0>, cudaFuncAttributeMaxDynamicSharedMemorySize, GEMM_SMEM);
    cudaFuncSetAttribute(mma_gemm<3>, cudaFuncAttributeMaxDynamicSharedMemorySize, GEMM_SMEM);

    const long long CVT_N = (long long)MTOT * D_ + (long long)NQKV * D_ + (long long)D_ * E_;
    dim3 t(256);
    cvt_all<<<(unsigned)((CVT_N / 8 + 255) / 256), t>>>(x, w_qkv, w_out);

    mma_gemm<0><<<dim3(NQKV / 128, MTOT / 128), t, GEMM_SMEM>>>(b_qkv, nullptr);
    fused_attn<<<dim3(S_ / 128, BHN), t, FA_SMEM>>>(attn_ext);
    mma_gemm<3><<<dim3(D_ / 128, MTOT / 128), t, GEMM_SMEM>>>(b_out, out_ext);
}